// round 15
// baseline (speedup 1.0000x reference)
#include <cuda_runtime.h>
#include <cuda_fp16.h>
#include <cstdint>
#include <cstddef>

#define NSITES 131072
#define HID    512
#define KTAPS  9
#define EPS    1e-5f
#define NUNITS 4096                      // 8 layers x 512 m-blocks

// ---------------------------------------------------------------------------
// Device-global scratch (allocation-free rule)
// ---------------------------------------------------------------------------
__device__ __align__(16) __half g_actA[(size_t)NSITES * HID];
__device__ __align__(16) __half g_actB[(size_t)NSITES * HID];
__device__ __align__(16) __half g_featH[(size_t)NSITES * 256];
#define W0H ((size_t)72  * 16384)
#define WLH ((size_t)144 * 16384)
__device__ __align__(16) __half g_Wp[W0H + 7 * WLH];
__device__ int g_flags[NUNITS];
__device__ unsigned g_ticket;

// ---------------------------------------------------------------------------
// Helpers (baseline PTX only — must pass ptxas at .target sm_103)
// ---------------------------------------------------------------------------
__device__ __forceinline__ uint32_t smem_u32(const void* p) {
    uint32_t a;
    asm("{ .reg .u64 t; cvta.to.shared.u64 t, %1; cvt.u32.u64 %0, t; }" : "=r"(a) : "l"(p));
    return a;
}
__device__ __forceinline__ void cp16(uint32_t dst, const void* src, int nbytes) {
    asm volatile("cp.async.cg.shared.global [%0], [%1], 16, %2;"
                 :: "r"(dst), "l"(src), "r"(nbytes));
}
__device__ __forceinline__ void mbar_init(uint32_t mbar, uint32_t cnt) {
    asm volatile("mbarrier.init.shared.b64 [%0], %1;" :: "r"(mbar), "r"(cnt) : "memory");
}
__device__ __forceinline__ void cp_arrive(uint32_t mbar) {
    asm volatile("cp.async.mbarrier.arrive.noinc.shared::cta.b64 [%0];"
                 :: "r"(mbar) : "memory");
}
__device__ __forceinline__ void mbar_arrive(uint32_t mbar) {
    asm volatile("mbarrier.arrive.shared.b64 _, [%0];" :: "r"(mbar) : "memory");
}
__device__ __forceinline__ void mbar_wait(uint32_t mbar, uint32_t parity) {
    asm volatile(
        "{\n\t.reg .pred P;\n\t"
        "LAB_%=:\n\t"
        "mbarrier.try_wait.parity.acquire.cta.shared::cta.b64 P, [%0], %1, 0x989680;\n\t"
        "@!P bra LAB_%=;\n\t}"
        :: "r"(mbar), "r"(parity) : "memory");
}
__device__ __forceinline__ int ld_acq(const int* p) {
    int v;
    asm volatile("ld.acquire.gpu.global.b32 %0, [%1];" : "=r"(v) : "l"(p) : "memory");
    return v;
}
__device__ __forceinline__ void st_rel(int* p, int v) {
    asm volatile("st.release.gpu.global.b32 [%0], %1;" :: "l"(p), "r"(v) : "memory");
}
__device__ __forceinline__ void ldmx4(uint32_t* r, uint32_t addr) {
    asm volatile("ldmatrix.sync.aligned.m8n8.x4.shared.b16 {%0,%1,%2,%3}, [%4];"
                 : "=r"(r[0]), "=r"(r[1]), "=r"(r[2]), "=r"(r[3]) : "r"(addr));
}
__device__ __forceinline__ void mma16(float* d, const uint32_t* a, const uint32_t* b) {
    asm volatile(
        "mma.sync.aligned.m16n8k16.row.col.f32.f16.f16.f32 "
        "{%0,%1,%2,%3}, {%4,%5,%6,%7}, {%8,%9}, {%0,%1,%2,%3};"
        : "+f"(d[0]), "+f"(d[1]), "+f"(d[2]), "+f"(d[3])
        : "r"(a[0]), "r"(a[1]), "r"(a[2]), "r"(a[3]), "r"(b[0]), "r"(b[1]));
}

// ---------------------------------------------------------------------------
// SMEM layout (bytes). B ring: 8 stages x 1 chunk x 10240B (R12 structure).
// ---------------------------------------------------------------------------
#define A_ROW_B   80
#define ZSLOT     528
#define A_ROWS    530
#define A_BUF_B   (A_ROWS * A_ROW_B)        // 42400
#define B_OFF     (2 * A_BUF_B)             // 84800
#define B_STAGE_B (128 * A_ROW_B)           // 10240
#define ASL_OFF   (B_OFF + 8 * B_STAGE_B)   // 166720
#define SG_OFF    (ASL_OFF + 9216)          // 175936
#define SB_OFF    (SG_OFF + 2048)           // 177984
#define MB_OFF    (SB_OFF + 2048)           // 180032
#define TK_OFF    (MB_OFF + 160)            // 180192
#define SMEM_BYTES (TK_OFF + 16)            // 180208
#define FB(s) (mb + (uint32_t)((s) * 8))
#define EB(s) (mb + 64u + (uint32_t)((s) * 8))
#define FA(b) (mb + 128u + (uint32_t)((b) * 8))
#define EA(b) (mb + 144u + (uint32_t)((b) * 8))

// ===========================================================================
// Persistent fused head (R12 structure): 148 CTAs, atomic-ticket units,
// 8-stage B ring (counter & 7), continuous producers across n-blocks/units,
// flag dataflow across layers. A halo load spread over taps 1-3.
// ===========================================================================
__global__ __launch_bounds__(256, 1)
void spconv_all(const __half* __restrict__ featH, const int* __restrict__ nbr,
                const __half* __restrict__ Wp,
                const float* __restrict__ gamma, const float* __restrict__ beta,
                __half* __restrict__ actA, __half* __restrict__ actB,
                float* __restrict__ outF)
{
    extern __shared__ char smc[];
    const uint32_t smbase = smem_u32(smc);
    const uint32_t mb = smbase + MB_OFF;
    uint32_t* aslot = (uint32_t*)(smc + ASL_OFF);
    float*    sgam  = (float*)(smc + SG_OFF);
    float*    sbet  = (float*)(smc + SB_OFF);
    int*      stkt  = (int*)(smc + TK_OFF);

    const int tid = threadIdx.x;
    if (tid < 20) {
        ((uint32_t*)(smc + ZSLOT * A_ROW_B))[tid] = 0;
        ((uint32_t*)(smc + A_BUF_B + ZSLOT * A_ROW_B))[tid] = 0;
    }
    if (tid < 8) { mbar_init(FB(tid), 256); mbar_init(EB(tid), 256); }
    if (tid < 2) { mbar_init(FA(tid), 256); mbar_init(EA(tid), 256); }
    if (tid == 0) *stkt = (int)atomicAdd(&g_ticket, 1u);
    __syncthreads();
    int u = *stkt;

    const int warp = tid >> 5, lane = tid & 31;
    const int wm  = (warp >> 1) * 64;
    const int wn  = (warp & 1) * 64;
    const int gid = lane >> 2;
    const int q   = lane & 3;
    const uint32_t a_lane = (uint32_t)((lane >> 4) * 16);
    const uint32_t b_loff = (uint32_t)(((lane & 7) + ((lane >> 4) & 1) * 8) * A_ROW_B
                                       + ((lane >> 3) & 1) * 16);

    int Ap = 0, Ac = 0, Bp = 0, Bc = 0;   // cumulative ring counters

    #pragma unroll 1
    while (u < NUNITS) {
        const int l = u >> 9, m = u & 511;
        const int m0   = m << 8;
        const int base = (m0 > 136) ? (m0 - 136) : 0;
        const int CIN   = l ? 512 : 256;
        const int NC0   = CIN >> 5;               // 8 or 16
        const int NITER = NC0 * KTAPS;
        const __half* X  = (l == 0) ? featH : ((l & 1) ? actA : actB);
        const __half* Wl = (l == 0) ? Wp : (Wp + W0H + (size_t)(l - 1) * WLH);
        const bool LAST = (l == 7);
        __half* OH = (l & 1) ? actB : actA;

        if (tid == 0) *stkt = (int)atomicAdd(&g_ticket, 1u);
        for (int i = tid; i < 512; i += 256) {
            sgam[i] = gamma[l * 512 + i];
            sbet[i] = beta[l * 512 + i];
        }
        #pragma unroll
        for (int t = 0; t < 9; t++) {
            const int i = t * 256 + tid;
            const int site = i / KTAPS, tap = i - site * KTAPS;
            const int nid = nbr[(size_t)m0 * KTAPS + i];
            const int slot = (nid < 0) ? ZSLOT : (nid - base);
            aslot[tap * 256 + site] = (uint32_t)(slot * A_ROW_B);
        }
        if (l > 0 && tid < 3) {
            const int mm = m - 1 + tid;
            if (mm >= 0 && mm < 512) {
                const int* fp = &g_flags[(l - 1) * 512 + mm];
                while (ld_acq(fp) == 0)
                    asm volatile("nanosleep.u32 128;");
            }
        }
        __syncthreads();
        const int u_next = *stkt;
        const bool pf_next = (u_next < NUNITS);
        const __half* WlN = Wp;
        if (pf_next) {
            const int ln = u_next >> 9;
            WlN = (ln == 0) ? Wp : (Wp + W0H + (size_t)(ln - 1) * WLH);
        }

        // full A halo load (prologue only)
        auto loadA = [&](int c0, int buf) {
            const uint32_t ab = smbase + (uint32_t)buf * A_BUF_B;
            #pragma unroll
            for (int t = 0; t < 9; t++) {
                const int g = t * 256 + tid;
                if (g < 528 * 4) {
                    const int row = g >> 2, seg = g & 3;
                    const long gr = (long)base + row;
                    const bool ok = gr < NSITES;
                    const __half* src = ok ? (X + gr * CIN + c0 * 32 + seg * 8) : X;
                    cp16(ab + (uint32_t)(row * A_ROW_B + seg * 16), src, ok ? 16 : 0);
                }
            }
        };
        // one third of an A halo load (704 granules): part in {0,1,2}
        auto loadApart = [&](int c0, int buf, int part) {
            const uint32_t ab = smbase + (uint32_t)buf * A_BUF_B;
            const int g0 = part * 704;
            #pragma unroll
            for (int t = 0; t < 3; t++) {
                const int g = g0 + t * 256 + tid;
                if (g < g0 + 704) {
                    const int row = g >> 2, seg = g & 3;
                    const long gr = (long)base + row;
                    const bool ok = gr < NSITES;
                    const __half* src = ok ? (X + gr * CIN + c0 * 32 + seg * 8) : X;
                    cp16(ab + (uint32_t)(row * A_ROW_B + seg * 16), src, ok ? 16 : 0);
                }
            }
        };
        auto loadBr = [&](int s, const __half* wc, int n0p) {
            const uint32_t bb = smbase + B_OFF + (uint32_t)s * B_STAGE_B;
            #pragma unroll
            for (int t = 0; t < 2; t++) {
                const int g = t * 256 + tid;
                const int nl = g >> 2, seg = g & 3;
                cp16(bb + (uint32_t)(nl * A_ROW_B + seg * 16),
                     wc + (size_t)(n0p + nl) * 32 + seg * 8, 16);
            }
        };

        // ---- A prologue: chunk 0 of this unit ----
        {
            const int b = Ap & 1, r = Ap >> 1;
            if (r >= 1) mbar_wait(EA(b), (uint32_t)((r - 1) & 1));
            loadA(0, b);
            cp_arrive(FA(b));
            Ap++;
        }
        // ---- B prologue: first unit of this CTA only ----
        if (Bp == 0) {
            #pragma unroll 1
            for (int p = 0; p < 6; p++) {
                loadBr(p, Wl + (size_t)p * 16384, 0);
                cp_arrive(FB(p));
                Bp++;
            }
        }
        int pcp = 6, pnb = 0;        // B produce cursor (pnb==4 => next unit)
        const int Ac0 = Ac;

        #pragma unroll 1
        for (int nb = 0; nb < 4; nb++) {
            const int n0 = nb << 7;
            float d[4][8][4];
            #pragma unroll
            for (int i = 0; i < 4; i++)
                #pragma unroll
                for (int j = 0; j < 8; j++)
                    #pragma unroll
                    for (int r = 0; r < 4; r++) d[i][j][r] = 0.f;

            #pragma unroll 1
            for (int it = 0; it < NITER; it++) {
                const int c0 = it / KTAPS, tap = it - c0 * KTAPS;

                // --- B producer: exactly one chunk per iteration ---
                if (pnb < 4 || (pnb == 4 && pcp < 6 && pf_next)) {
                    const __half* wsrc = (pnb < 4) ? (Wl + (size_t)pcp * 16384)
                                                   : (WlN + (size_t)pcp * 16384);
                    const int n0p = (pnb < 4) ? (pnb << 7) : 0;
                    const int s = Bp & 7, r = Bp >> 3;
                    if (r >= 1) mbar_wait(EB(s), (uint32_t)((r - 1) & 1));
                    loadBr(s, wsrc, n0p);
                    cp_arrive(FB(s));
                    Bp++;
                    const int lim = (pnb < 4) ? NITER : 6;
                    if (++pcp == lim) { pcp = 0; pnb++; }
                }
                // --- A producer: spread over taps 1-3 (1/3 of the halo each) ---
                if (tap >= 1 && tap <= 3) {
                    const int la = Ac - Ac0;
                    if (la + 1 < 4 * NC0) {
                        const int b = Ap & 1;
                        if (tap == 1) {
                            const int r = Ap >> 1;
                            if (r >= 1) mbar_wait(EA(b), (uint32_t)((r - 1) & 1));
                        }
                        loadApart((la + 1) & (NC0 - 1), b, tap - 1);
                        if (tap == 3) { cp_arrive(FA(b)); Ap++; }
                    }
                }

                // --- consumers ---
                if (tap == 0) mbar_wait(FA(Ac & 1), (uint32_t)((Ac >> 1) & 1));
                mbar_wait(FB(Bc & 7), (uint32_t)((Bc >> 3) & 1));

                const uint32_t ab = smbase + (uint32_t)(Ac & 1) * A_BUF_B;
                const uint32_t bb = smbase + B_OFF + (uint32_t)(Bc & 7) * B_STAGE_B;
                uint32_t asl[4];
                #pragma unroll
                for (int mt = 0; mt < 4; mt++)
                    asl[mt] = aslot[tap * 256 + wm + mt * 16 + (lane & 15)];
                #pragma unroll
                for (int s16 = 0; s16 < 2; s16++) {
                    uint32_t a[4][4];
                    #pragma unroll
                    for (int mt = 0; mt < 4; mt++)
                        ldmx4(a[mt], ab + asl[mt] + (uint32_t)(s16 * 32) + a_lane);
                    uint32_t b[8][2];
                    #pragma unroll
                    for (int np = 0; np < 4; np++) {
                        uint32_t r[4];
                        ldmx4(r, bb + (uint32_t)((wn + np * 16) * A_ROW_B + s16 * 32)
                                 + b_loff);
                        b[2 * np][0] = r[0];     b[2 * np][1] = r[1];
                        b[2 * np + 1][0] = r[2]; b[2 * np + 1][1] = r[3];
                    }
                    #pragma unroll
                    for (int nt = 0; nt < 8; nt++)
                        #pragma unroll
                        for (int mt = 0; mt < 4; mt++)
                            mma16(d[mt][nt], a[mt], b[nt]);
                }

                mbar_arrive(EB(Bc & 7)); Bc++;
                if (tap == KTAPS - 1) { mbar_arrive(EA(Ac & 1)); Ac++; }
            }

            // ---- fused GroupNorm(16-ch) + ReLU epilogue for this n-block ----
            #pragma unroll
            for (int mt = 0; mt < 4; mt++) {
                #pragma unroll
                for (int h = 0; h < 2; h++) {
                    const int row = m0 + wm + mt * 16 + gid + h * 8;
                    const size_t rbase = (size_t)row * HID + n0 + wn;
                    #pragma unroll
                    for (int g = 0; g < 4; g++) {
                        const float v0 = d[mt][2 * g    ][2 * h];
                        const float v1 = d[mt][2 * g    ][2 * h + 1];
                        const float v2 = d[mt][2 * g + 1][2 * h];
                        const float v3 = d[mt][2 * g + 1][2 * h + 1];
                        float s  = v0 + v1 + v2 + v3;
                        float ss = v0 * v0 + v1 * v1 + v2 * v2 + v3 * v3;
                        s  += __shfl_xor_sync(0xffffffffu, s, 1);
                        ss += __shfl_xor_sync(0xffffffffu, ss, 1);
                        s  += __shfl_xor_sync(0xffffffffu, s, 2);
                        ss += __shfl_xor_sync(0xffffffffu, ss, 2);
                        const float mu  = s * (1.f / 16.f);
                        const float var = ss * (1.f / 16.f) - mu * mu;
                        const float rs  = rsqrtf(var + EPS);
                        const int cb = n0 + wn + 16 * g + 2 * q;
                        const float o0 = fmaxf(fmaf((v0 - mu) * rs, sgam[cb],     sbet[cb]),     0.f);
                        const float o1 = fmaxf(fmaf((v1 - mu) * rs, sgam[cb + 1], sbet[cb + 1]), 0.f);
                        const float o2 = fmaxf(fmaf((v2 - mu) * rs, sgam[cb + 8], sbet[cb + 8]), 0.f);
                        const float o3 = fmaxf(fmaf((v3 - mu) * rs, sgam[cb + 9], sbet[cb + 9]), 0.f);
                        if (LAST) {
                            *(float2*)(outF + rbase + 16 * g + 2 * q)     = make_float2(o0, o1);
                            *(float2*)(outF + rbase + 16 * g + 8 + 2 * q) = make_float2(o2, o3);
                        } else {
                            *(__half2*)(OH + rbase + 16 * g + 2 * q)     = __floats2half2_rn(o0, o1);
                            *(__half2*)(OH + rbase + 16 * g + 8 + 2 * q) = __floats2half2_rn(o2, o3);
                        }
                    }
                }
            }
        }

        __threadfence();
        __syncthreads();
        if (tid == 0) st_rel(&g_flags[u], 1);
        u = u_next;
    }
}

// ---------------------------------------------------------------------------
// Prep kernels (R12 originals: separate w_prep launches)
// ---------------------------------------------------------------------------
__global__ void reset_flags()
{
    const int i = blockIdx.x * 256 + threadIdx.x;
    g_flags[i] = 0;
    if (i == 0) g_ticket = 0u;
}
__global__ void w_prep(const float* __restrict__ W, __half* __restrict__ Wp, int CPT)
{
    __shared__ float t[32][33];
    const int bx = blockIdx.x;
    const int by = blockIdx.y;
    const int x = threadIdx.x, y = threadIdx.y;
    #pragma unroll
    for (int i = 0; i < 32; i += 8)
        t[y + i][x] = W[(size_t)(by * 32 + y + i) * 512 + bx * 32 + x];
    __syncthreads();
    const int tap = by / CPT, c0 = by - tap * CPT;
    const int cpos = c0 * KTAPS + tap;
    #pragma unroll
    for (int i = 0; i < 32; i += 8) {
        const int nl = y + i, kk = x;
        Wp[(size_t)cpos * 16384 + (size_t)(bx * 32 + nl) * 32 + kk] =
            __float2half_rn(t[kk][nl]);
    }
}
__global__ void f2h(const float* __restrict__ src, __half* __restrict__ dst)
{
    const int t = blockIdx.x * blockDim.x + threadIdx.x;
    const float4* s = (const float4*)src + 2 * (size_t)t;
    const float4 v0 = s[0], v1 = s[1];
    __half2* o = (__half2*)dst + 4 * (size_t)t;
    o[0] = __floats2half2_rn(v0.x, v0.y);
    o[1] = __floats2half2_rn(v0.z, v0.w);
    o[2] = __floats2half2_rn(v1.x, v1.y);
    o[3] = __floats2half2_rn(v1.z, v1.w);
}

// ===========================================================================
// kernel_launch: prep + flag/ticket reset + one persistent fused kernel.
// ===========================================================================
extern "C" void kernel_launch(void* const* d_in, const int* in_sizes, int n_in,
                              void* d_out, int out_size)
{
    const float* feat  = (const float*)d_in[0];
    const int*   nbr   = (const int*)  d_in[1];
    const float* w0    = (const float*)d_in[2];
    const float* wrest = (const float*)d_in[3];
    const float* gamma = (const float*)d_in[4];
    const float* beta  = (const float*)d_in[5];

    __half *actA, *actB, *featH, *Wp;
    cudaGetSymbolAddress((void**)&actA, g_actA);
    cudaGetSymbolAddress((void**)&actB, g_actB);
    cudaGetSymbolAddress((void**)&featH, g_featH);
    cudaGetSymbolAddress((void**)&Wp, g_Wp);

    cudaFuncSetAttribute(spconv_all,
                         cudaFuncAttributeMaxDynamicSharedMemorySize, SMEM_BYTES);

    f2h<<<(NSITES * 256 / 8) / 256, 256>>>(feat, featH);
    w_prep<<<dim3(16, 72), dim3(32, 8)>>>(w0, Wp, 8);
    for (int l = 0; l < 7; l++)
        w_prep<<<dim3(16, 144), dim3(32, 8)>>>(
            wrest + (size_t)l * 4608 * 512, Wp + W0H + (size_t)l * WLH, 16);
    reset_flags<<<NUNITS / 256, 256>>>();

    spconv_all<<<148, 256, SMEM_BYTES>>>(featH, nbr, Wp, gamma, beta,
                                         actA, actB, (float*)d_out);
}

// round 16
// speedup vs baseline: 1.2378x; 1.2378x over previous
#include <cuda_runtime.h>
#include <cuda_fp16.h>
#include <cstdint>
#include <cstddef>

#define NSITES 131072
#define HID    512
#define KTAPS  9
#define EPS    1e-5f
#define NUNITS 4096                      // 8 layers x 512 m-blocks

// ---------------------------------------------------------------------------
// Device-global scratch (allocation-free rule)
// ---------------------------------------------------------------------------
__device__ __align__(16) __half g_actA[(size_t)NSITES * HID];
__device__ __align__(16) __half g_actB[(size_t)NSITES * HID];
__device__ __align__(16) __half g_featH[(size_t)NSITES * 256];
#define W0H ((size_t)72  * 16384)
#define WLH ((size_t)144 * 16384)
__device__ __align__(16) __half g_Wp[W0H + 7 * WLH];
__device__ int g_flags[NUNITS];
__device__ unsigned g_ticket;

// ---------------------------------------------------------------------------
// Helpers (baseline PTX only — must pass ptxas at .target sm_103)
// ---------------------------------------------------------------------------
__device__ __forceinline__ uint32_t smem_u32(const void* p) {
    uint32_t a;
    asm("{ .reg .u64 t; cvta.to.shared.u64 t, %1; cvt.u32.u64 %0, t; }" : "=r"(a) : "l"(p));
    return a;
}
__device__ __forceinline__ void cp16(uint32_t dst, const void* src, int nbytes) {
    asm volatile("cp.async.cg.shared.global [%0], [%1], 16, %2;"
                 :: "r"(dst), "l"(src), "r"(nbytes));
}
__device__ __forceinline__ void mbar_init(uint32_t mbar, uint32_t cnt) {
    asm volatile("mbarrier.init.shared.b64 [%0], %1;" :: "r"(mbar), "r"(cnt) : "memory");
}
__device__ __forceinline__ void cp_arrive(uint32_t mbar) {
    asm volatile("cp.async.mbarrier.arrive.noinc.shared::cta.b64 [%0];"
                 :: "r"(mbar) : "memory");
}
__device__ __forceinline__ void mbar_arrive(uint32_t mbar) {
    asm volatile("mbarrier.arrive.shared.b64 _, [%0];" :: "r"(mbar) : "memory");
}
__device__ __forceinline__ void mbar_wait(uint32_t mbar, uint32_t parity) {
    asm volatile(
        "{\n\t.reg .pred P;\n\t"
        "LAB_%=:\n\t"
        "mbarrier.try_wait.parity.acquire.cta.shared::cta.b64 P, [%0], %1, 0x989680;\n\t"
        "@!P bra LAB_%=;\n\t}"
        :: "r"(mbar), "r"(parity) : "memory");
}
__device__ __forceinline__ int ld_acq(const int* p) {
    int v;
    asm volatile("ld.acquire.gpu.global.b32 %0, [%1];" : "=r"(v) : "l"(p) : "memory");
    return v;
}
__device__ __forceinline__ void st_rel(int* p, int v) {
    asm volatile("st.release.gpu.global.b32 [%0], %1;" :: "l"(p), "r"(v) : "memory");
}
__device__ __forceinline__ void ldmx4(uint32_t* r, uint32_t addr) {
    asm volatile("ldmatrix.sync.aligned.m8n8.x4.shared.b16 {%0,%1,%2,%3}, [%4];"
                 : "=r"(r[0]), "=r"(r[1]), "=r"(r[2]), "=r"(r[3]) : "r"(addr));
}
__device__ __forceinline__ void mma16(float* d, const uint32_t* a, const uint32_t* b) {
    asm volatile(
        "mma.sync.aligned.m16n8k16.row.col.f32.f16.f16.f32 "
        "{%0,%1,%2,%3}, {%4,%5,%6,%7}, {%8,%9}, {%0,%1,%2,%3};"
        : "+f"(d[0]), "+f"(d[1]), "+f"(d[2]), "+f"(d[3])
        : "r"(a[0]), "r"(a[1]), "r"(a[2]), "r"(a[3]), "r"(b[0]), "r"(b[1]));
}

// ---------------------------------------------------------------------------
// SMEM layout (bytes)
// ---------------------------------------------------------------------------
#define A_ROW_B   80
#define ZSLOT     528
#define A_ROWS    530
#define A_BUF_B   (A_ROWS * A_ROW_B)        // 42400
#define B_OFF     (2 * A_BUF_B)             // 84800
#define B_STAGE_B (128 * A_ROW_B)           // 10240
#define ASL_OFF   (B_OFF + 8 * B_STAGE_B)   // 166720
#define SG_OFF    (ASL_OFF + 9216)          // 175936 (512 f32)
#define SB_OFF    (SG_OFF + 2048)           // 177984
#define MB_OFF    (SB_OFF + 2048)           // 180032
#define TK_OFF    (MB_OFF + 160)            // 180192 (ticket int)
#define SMEM_BYTES (TK_OFF + 16)            // 180208
#define FB(s) (mb + (uint32_t)((s) * 8))
#define EB(s) (mb + 64u + (uint32_t)((s) * 8))
#define FA(b) (mb + 128u + (uint32_t)((b) * 8))
#define EA(b) (mb + 144u + (uint32_t)((b) * 8))

// ===========================================================================
// Persistent fused head: 148 CTAs, atomic-ticket units = (layer, m-block).
// Continuous A/B producer streams (B prefetches across units); cumulative
// ring counters Ap/Ac/Bp/Bc; flag dataflow across layers.
// ===========================================================================
__global__ __launch_bounds__(256, 1)
void spconv_all(const __half* __restrict__ featH, const int* __restrict__ nbr,
                const __half* __restrict__ Wp,
                const float* __restrict__ gamma, const float* __restrict__ beta,
                __half* __restrict__ actA, __half* __restrict__ actB,
                float* __restrict__ outF)
{
    extern __shared__ char smc[];
    const uint32_t smbase = smem_u32(smc);
    const uint32_t mb = smbase + MB_OFF;
    uint32_t* aslot = (uint32_t*)(smc + ASL_OFF);
    float*    sgam  = (float*)(smc + SG_OFF);
    float*    sbet  = (float*)(smc + SB_OFF);
    int*      stkt  = (int*)(smc + TK_OFF);

    const int tid = threadIdx.x;
    if (tid < 20) {
        ((uint32_t*)(smc + ZSLOT * A_ROW_B))[tid] = 0;
        ((uint32_t*)(smc + A_BUF_B + ZSLOT * A_ROW_B))[tid] = 0;
    }
    if (tid < 8) { mbar_init(FB(tid), 256); mbar_init(EB(tid), 256); }
    if (tid < 2) { mbar_init(FA(tid), 256); mbar_init(EA(tid), 256); }
    if (tid == 0) *stkt = (int)atomicAdd(&g_ticket, 1u);
    __syncthreads();
    int u = *stkt;

    const int warp = tid >> 5, lane = tid & 31;
    const int wm  = (warp >> 1) * 64;
    const int wn  = (warp & 1) * 64;
    const int gid = lane >> 2;
    const int q   = lane & 3;
    const uint32_t a_lane = (uint32_t)((lane >> 4) * 16);
    const uint32_t b_loff = (uint32_t)(((lane & 7) + ((lane >> 4) & 1) * 8) * A_ROW_B
                                       + ((lane >> 3) & 1) * 16);

    int Ap = 0, Ac = 0;     // A chunk counters (cumulative)
    int Bp = 0;             // B PAIR producer counter (cumulative)
    int Bc = 0;             // B CHUNK consumer counter (cumulative)

    #pragma unroll 1
    while (u < NUNITS) {
        const int l = u >> 9, m = u & 511;
        const int m0   = m << 8;
        const int base = (m0 > 136) ? (m0 - 136) : 0;
        const int CIN   = l ? 512 : 256;
        const int NC0   = CIN >> 5;               // 8 or 16 (power of 2)
        const int NITER = NC0 * KTAPS;
        const __half* X  = (l == 0) ? featH : ((l & 1) ? actA : actB);
        const __half* Wl = (l == 0) ? Wp : (Wp + W0H + (size_t)(l - 1) * WLH);
        const bool LAST = (l == 7);
        __half* OH = (l & 1) ? actB : actA;

        if (tid == 0) *stkt = (int)atomicAdd(&g_ticket, 1u);
        for (int i = tid; i < 512; i += 256) {
            sgam[i] = gamma[l * 512 + i];
            sbet[i] = beta[l * 512 + i];
        }
        #pragma unroll
        for (int t = 0; t < 9; t++) {
            const int i = t * 256 + tid;
            const int site = i / KTAPS, tap = i - site * KTAPS;
            const int nid = nbr[(size_t)m0 * KTAPS + i];
            const int slot = (nid < 0) ? ZSLOT : (nid - base);
            aslot[tap * 256 + site] = (uint32_t)(slot * A_ROW_B);
        }
        if (l > 0 && tid < 3) {
            const int mm = m - 1 + tid;
            if (mm >= 0 && mm < 512) {
                const int* fp = &g_flags[(l - 1) * 512 + mm];
                while (ld_acq(fp) == 0)
                    asm volatile("nanosleep.u32 128;");
            }
        }
        __syncthreads();
        const int u_next = *stkt;
        const bool pf_next = (u_next < NUNITS);
        const __half* WlN = Wp;
        if (pf_next) {
            const int ln = u_next >> 9;
            WlN = (ln == 0) ? Wp : (Wp + W0H + (size_t)(ln - 1) * WLH);
        }

        auto loadA = [&](int c0, int buf) {
            const uint32_t ab = smbase + (uint32_t)buf * A_BUF_B;
            #pragma unroll
            for (int t = 0; t < 9; t++) {
                const int g = t * 256 + tid;
                if (g < 528 * 4) {
                    const int row = g >> 2, seg = g & 3;
                    const long gr = (long)base + row;
                    const bool ok = gr < NSITES;
                    const __half* src = ok ? (X + gr * CIN + c0 * 32 + seg * 8) : X;
                    cp16(ab + (uint32_t)(row * A_ROW_B + seg * 16), src, ok ? 16 : 0);
                }
            }
        };
        auto loadBr = [&](int s, const __half* wc, int n0p) {
            const uint32_t bb = smbase + B_OFF + (uint32_t)s * B_STAGE_B;
            #pragma unroll
            for (int t = 0; t < 2; t++) {
                const int g = t * 256 + tid;
                const int nl = g >> 2, seg = g & 3;
                cp16(bb + (uint32_t)(nl * A_ROW_B + seg * 16),
                     wc + (size_t)(n0p + nl) * 32 + seg * 8, 16);
            }
        };

        // ---- A prologue: chunk 0 of this unit ----
        {
            const int b = Ap & 1, r = Ap >> 1;
            if (r >= 1) mbar_wait(EA(b), (uint32_t)((r - 1) & 1));
            loadA(0, b);
            cp_arrive(FA(b));
            Ap++;
        }
        // ---- B prologue: first unit of this CTA only ----
        if (Bp == 0) {
            #pragma unroll 1
            for (int p = 0; p < 6; p++) {
                loadBr(p, Wl + (size_t)p * 16384, 0);
                cp_arrive(FB(p));
                Bp++;
            }
        }
        int pcp = 6, pnb = 0;        // B produce cursor (pnb==4 => next unit)
        const int Ac0 = Ac;

        #pragma unroll 1
        for (int nb = 0; nb < 4; nb++) {
            const int n0 = nb << 7;
            float d[4][8][4];
            #pragma unroll
            for (int i = 0; i < 4; i++)
                #pragma unroll
                for (int j = 0; j < 8; j++)
                    #pragma unroll
                    for (int r = 0; r < 4; r++) d[i][j][r] = 0.f;

            #pragma unroll 1
            for (int it = 0; it < NITER; it++) {
                const int c0 = it / KTAPS, tap = it - c0 * KTAPS;

                // --- B producer: exactly one chunk per iteration ---
                if (pnb < 4 || (pnb == 4 && pcp < 6 && pf_next)) {
                    const __half* wsrc = (pnb < 4) ? (Wl + (size_t)pcp * 16384)
                                                   : (WlN + (size_t)pcp * 16384);
                    const int n0p = (pnb < 4) ? (pnb << 7) : 0;
                    const int s = Bp & 7, r = Bp >> 3;
                    if (r >= 1) mbar_wait(EB(s), (uint32_t)((r - 1) & 1));
                    loadBr(s, wsrc, n0p);
                    cp_arrive(FB(s));
                    Bp++;
                    const int lim = (pnb < 4) ? NITER : 6;
                    if (++pcp == lim) { pcp = 0; pnb++; }
                }
                // --- A producer: next chunk in the flattened per-unit stream ---
                if (tap == 1) {
                    const int la = Ac - Ac0;          // chunk currently consumed
                    if (la + 1 < 4 * NC0) {
                        const int b = Ap & 1, r = Ap >> 1;
                        if (r >= 1) mbar_wait(EA(b), (uint32_t)((r - 1) & 1));
                        loadA((la + 1) & (NC0 - 1), b);
                        cp_arrive(FA(b));
                        Ap++;
                    }
                }

                // --- consumers ---
                if (tap == 0) mbar_wait(FA(Ac & 1), (uint32_t)((Ac >> 1) & 1));
                mbar_wait(FB(Bc & 7), (uint32_t)((Bc >> 3) & 1));

                const uint32_t ab = smbase + (uint32_t)(Ac & 1) * A_BUF_B;
                const uint32_t bb = smbase + B_OFF + (uint32_t)(Bc & 7) * B_STAGE_B;
                uint32_t asl[4];
                #pragma unroll
                for (int mt = 0; mt < 4; mt++)
                    asl[mt] = aslot[tap * 256 + wm + mt * 16 + (lane & 15)];
                #pragma unroll
                for (int s16 = 0; s16 < 2; s16++) {
                    uint32_t a[4][4];
                    #pragma unroll
                    for (int mt = 0; mt < 4; mt++)
                        ldmx4(a[mt], ab + asl[mt] + (uint32_t)(s16 * 32) + a_lane);
                    uint32_t b[8][2];
                    #pragma unroll
                    for (int np = 0; np < 4; np++) {
                        uint32_t r[4];
                        ldmx4(r, bb + (uint32_t)((wn + np * 16) * A_ROW_B + s16 * 32)
                                 + b_loff);
                        b[2 * np][0] = r[0];     b[2 * np][1] = r[1];
                        b[2 * np + 1][0] = r[2]; b[2 * np + 1][1] = r[3];
                    }
                    #pragma unroll
                    for (int nt = 0; nt < 8; nt++)
                        #pragma unroll
                        for (int mt = 0; mt < 4; mt++)
                            mma16(d[mt][nt], a[mt], b[nt]);
                }

                mbar_arrive(EB(Bc & 7)); Bc++;
                if (tap == KTAPS - 1) { mbar_arrive(EA(Ac & 1)); Ac++; }
            }

            // ---- fused GroupNorm(16-ch) + ReLU epilogue for this n-block ----
            #pragma unroll
            for (int mt = 0; mt < 4; mt++) {
                #pragma unroll
                for (int h = 0; h < 2; h++) {
                    const int row = m0 + wm + mt * 16 + gid + h * 8;
                    const size_t rbase = (size_t)row * HID + n0 + wn;
                    #pragma unroll
                    for (int g = 0; g < 4; g++) {
                        const float v0 = d[mt][2 * g    ][2 * h];
                        const float v1 = d[mt][2 * g    ][2 * h + 1];
                        const float v2 = d[mt][2 * g + 1][2 * h];
                        const float v3 = d[mt][2 * g + 1][2 * h + 1];
                        float s  = v0 + v1 + v2 + v3;
                        float ss = v0 * v0 + v1 * v1 + v2 * v2 + v3 * v3;
                        s  += __shfl_xor_sync(0xffffffffu, s, 1);
                        ss += __shfl_xor_sync(0xffffffffu, ss, 1);
                        s  += __shfl_xor_sync(0xffffffffu, s, 2);
                        ss += __shfl_xor_sync(0xffffffffu, ss, 2);
                        const float mu  = s * (1.f / 16.f);
                        const float var = ss * (1.f / 16.f) - mu * mu;
                        const float rs  = rsqrtf(var + EPS);
                        const int cb = n0 + wn + 16 * g + 2 * q;
                        const float o0 = fmaxf(fmaf((v0 - mu) * rs, sgam[cb],     sbet[cb]),     0.f);
                        const float o1 = fmaxf(fmaf((v1 - mu) * rs, sgam[cb + 1], sbet[cb + 1]), 0.f);
                        const float o2 = fmaxf(fmaf((v2 - mu) * rs, sgam[cb + 8], sbet[cb + 8]), 0.f);
                        const float o3 = fmaxf(fmaf((v3 - mu) * rs, sgam[cb + 9], sbet[cb + 9]), 0.f);
                        if (LAST) {
                            *(float2*)(outF + rbase + 16 * g + 2 * q)     = make_float2(o0, o1);
                            *(float2*)(outF + rbase + 16 * g + 8 + 2 * q) = make_float2(o2, o3);
                        } else {
                            *(__half2*)(OH + rbase + 16 * g + 2 * q)     = __floats2half2_rn(o0, o1);
                            *(__half2*)(OH + rbase + 16 * g + 8 + 2 * q) = __floats2half2_rn(o2, o3);
                        }
                    }
                }
            }
        }

        __threadfence();
        __syncthreads();
        if (tid == 0) st_rel(&g_flags[u], 1);
        u = u_next;
    }
}

// ---------------------------------------------------------------------------
// Prep kernels
// ---------------------------------------------------------------------------
__global__ void reset_flags()
{
    const int i = blockIdx.x * 256 + threadIdx.x;
    g_flags[i] = 0;
    if (i == 0) g_ticket = 0u;
}
__global__ void w_prep(const float* __restrict__ W, __half* __restrict__ Wp, int CPT)
{
    __shared__ float t[32][33];
    const int bx = blockIdx.x;
    const int by = blockIdx.y;
    const int x = threadIdx.x, y = threadIdx.y;
    #pragma unroll
    for (int i = 0; i < 32; i += 8)
        t[y + i][x] = W[(size_t)(by * 32 + y + i) * 512 + bx * 32 + x];
    __syncthreads();
    const int tap = by / CPT, c0 = by - tap * CPT;
    const int cpos = c0 * KTAPS + tap;
    #pragma unroll
    for (int i = 0; i < 32; i += 8) {
        const int nl = y + i, kk = x;
        Wp[(size_t)cpos * 16384 + (size_t)(bx * 32 + nl) * 32 + kk] =
            __float2half_rn(t[kk][nl]);
    }
}
__global__ void f2h(const float* __restrict__ src, __half* __restrict__ dst)
{
    const int t = blockIdx.x * blockDim.x + threadIdx.x;
    const float4* s = (const float4*)src + 2 * (size_t)t;
    const float4 v0 = s[0], v1 = s[1];
    __half2* o = (__half2*)dst + 4 * (size_t)t;
    o[0] = __floats2half2_rn(v0.x, v0.y);
    o[1] = __floats2half2_rn(v0.z, v0.w);
    o[2] = __floats2half2_rn(v1.x, v1.y);
    o[3] = __floats2half2_rn(v1.z, v1.w);
}

// ===========================================================================
// kernel_launch: prep + flag/ticket reset + one persistent fused kernel.
// ===========================================================================
extern "C" void kernel_launch(void* const* d_in, const int* in_sizes, int n_in,
                              void* d_out, int out_size)
{
    const float* feat  = (const float*)d_in[0];
    const int*   nbr   = (const int*)  d_in[1];
    const float* w0    = (const float*)d_in[2];
    const float* wrest = (const float*)d_in[3];
    const float* gamma = (const float*)d_in[4];
    const float* beta  = (const float*)d_in[5];

    __half *actA, *actB, *featH, *Wp;
    cudaGetSymbolAddress((void**)&actA, g_actA);
    cudaGetSymbolAddress((void**)&actB, g_actB);
    cudaGetSymbolAddress((void**)&featH, g_featH);
    cudaGetSymbolAddress((void**)&Wp, g_Wp);

    cudaFuncSetAttribute(spconv_all,
                         cudaFuncAttributeMaxDynamicSharedMemorySize, SMEM_BYTES);

    f2h<<<(NSITES * 256 / 8) / 256, 256>>>(feat, featH);
    w_prep<<<dim3(16, 72), dim3(32, 8)>>>(w0, Wp, 8);
    for (int l = 0; l < 7; l++)
        w_prep<<<dim3(16, 144), dim3(32, 8)>>>(
            wrest + (size_t)l * 4608 * 512, Wp + W0H + (size_t)l * WLH, 16);
    reset_flags<<<NUNITS / 256, 256>>>();

    spconv_all<<<148, 256, SMEM_BYTES>>>(featH, nbr, Wp, gamma, beta,
                                         actA, actB, (float*)d_out);
}

// round 17
// speedup vs baseline: 1.2811x; 1.0350x over previous
#include <cuda_runtime.h>
#include <cuda_fp16.h>
#include <cstdint>
#include <cstddef>

#define NSITES 131072
#define HID    512
#define KTAPS  9
#define EPS    1e-5f
#define NUNITS 4096                      // 8 layers x 512 m-blocks

// ---------------------------------------------------------------------------
// Device-global scratch (allocation-free rule)
// ---------------------------------------------------------------------------
__device__ __align__(16) __half g_actA[(size_t)NSITES * HID];
__device__ __align__(16) __half g_actB[(size_t)NSITES * HID];
__device__ __align__(16) __half g_featH[(size_t)NSITES * 256];
#define W0H ((size_t)72  * 16384)
#define WLH ((size_t)144 * 16384)
__device__ __align__(16) __half g_Wp[W0H + 7 * WLH];
__device__ int g_flags[NUNITS];
__device__ unsigned g_ticket;

// ---------------------------------------------------------------------------
// Helpers (baseline PTX only — must pass ptxas at .target sm_103)
// ---------------------------------------------------------------------------
__device__ __forceinline__ uint32_t smem_u32(const void* p) {
    uint32_t a;
    asm("{ .reg .u64 t; cvta.to.shared.u64 t, %1; cvt.u32.u64 %0, t; }" : "=r"(a) : "l"(p));
    return a;
}
__device__ __forceinline__ void cp16(uint32_t dst, const void* src, int nbytes) {
    asm volatile("cp.async.cg.shared.global [%0], [%1], 16, %2;"
                 :: "r"(dst), "l"(src), "r"(nbytes));
}
__device__ __forceinline__ void mbar_init(uint32_t mbar, uint32_t cnt) {
    asm volatile("mbarrier.init.shared.b64 [%0], %1;" :: "r"(mbar), "r"(cnt) : "memory");
}
__device__ __forceinline__ void cp_arrive(uint32_t mbar) {
    asm volatile("cp.async.mbarrier.arrive.noinc.shared::cta.b64 [%0];"
                 :: "r"(mbar) : "memory");
}
__device__ __forceinline__ void mbar_arrive(uint32_t mbar) {
    asm volatile("mbarrier.arrive.shared.b64 _, [%0];" :: "r"(mbar) : "memory");
}
__device__ __forceinline__ void mbar_wait(uint32_t mbar, uint32_t parity) {
    asm volatile(
        "{\n\t.reg .pred P;\n\t"
        "LAB_%=:\n\t"
        "mbarrier.try_wait.parity.acquire.cta.shared::cta.b64 P, [%0], %1, 0x989680;\n\t"
        "@!P bra LAB_%=;\n\t}"
        :: "r"(mbar), "r"(parity) : "memory");
}
__device__ __forceinline__ int ld_acq(const int* p) {
    int v;
    asm volatile("ld.acquire.gpu.global.b32 %0, [%1];" : "=r"(v) : "l"(p) : "memory");
    return v;
}
__device__ __forceinline__ void st_rel(int* p, int v) {
    asm volatile("st.release.gpu.global.b32 [%0], %1;" :: "l"(p), "r"(v) : "memory");
}
__device__ __forceinline__ void ldmx4(uint32_t* r, uint32_t addr) {
    asm volatile("ldmatrix.sync.aligned.m8n8.x4.shared.b16 {%0,%1,%2,%3}, [%4];"
                 : "=r"(r[0]), "=r"(r[1]), "=r"(r[2]), "=r"(r[3]) : "r"(addr));
}
__device__ __forceinline__ void mma16(float* d, const uint32_t* a, const uint32_t* b) {
    asm volatile(
        "mma.sync.aligned.m16n8k16.row.col.f32.f16.f16.f32 "
        "{%0,%1,%2,%3}, {%4,%5,%6,%7}, {%8,%9}, {%0,%1,%2,%3};"
        : "+f"(d[0]), "+f"(d[1]), "+f"(d[2]), "+f"(d[3])
        : "r"(a[0]), "r"(a[1]), "r"(a[2]), "r"(a[3]), "r"(b[0]), "r"(b[1]));
}

// ---------------------------------------------------------------------------
// SMEM layout (bytes)
// ---------------------------------------------------------------------------
#define A_ROW_B   80
#define ZSLOT     528
#define A_ROWS    530
#define A_BUF_B   (A_ROWS * A_ROW_B)        // 42400
#define B_OFF     (2 * A_BUF_B)             // 84800
#define B_STAGE_B (128 * A_ROW_B)           // 10240
#define ASL_OFF   (B_OFF + 8 * B_STAGE_B)   // 166720
#define SG_OFF    (ASL_OFF + 9216)          // 175936 (512 f32)
#define SB_OFF    (SG_OFF + 2048)           // 177984
#define MB_OFF    (SB_OFF + 2048)           // 180032
#define TK_OFF    (MB_OFF + 160)            // 180192 (ticket int)
#define SMEM_BYTES (TK_OFF + 16)            // 180208
#define FB(s) (mb + (uint32_t)((s) * 8))
#define EB(s) (mb + 64u + (uint32_t)((s) * 8))
#define FA(b) (mb + 128u + (uint32_t)((b) * 8))
#define EA(b) (mb + 144u + (uint32_t)((b) * 8))

// ===========================================================================
// Persistent fused head: one CTA per SM, atomic-ticket units = (layer,
// m-block). Continuous A/B producer streams (B prefetches across units);
// cumulative ring counters Ap/Ac/Bp/Bc; flag dataflow across layers.
// ===========================================================================
__global__ __launch_bounds__(256, 1)
void spconv_all(const __half* __restrict__ featH, const int* __restrict__ nbr,
                const __half* __restrict__ Wp,
                const float* __restrict__ gamma, const float* __restrict__ beta,
                __half* __restrict__ actA, __half* __restrict__ actB,
                float* __restrict__ outF)
{
    extern __shared__ char smc[];
    const uint32_t smbase = smem_u32(smc);
    const uint32_t mb = smbase + MB_OFF;
    uint32_t* aslot = (uint32_t*)(smc + ASL_OFF);
    float*    sgam  = (float*)(smc + SG_OFF);
    float*    sbet  = (float*)(smc + SB_OFF);
    int*      stkt  = (int*)(smc + TK_OFF);

    const int tid = threadIdx.x;
    if (tid < 20) {
        ((uint32_t*)(smc + ZSLOT * A_ROW_B))[tid] = 0;
        ((uint32_t*)(smc + A_BUF_B + ZSLOT * A_ROW_B))[tid] = 0;
    }
    if (tid < 8) { mbar_init(FB(tid), 256); mbar_init(EB(tid), 256); }
    if (tid < 2) { mbar_init(FA(tid), 256); mbar_init(EA(tid), 256); }
    if (tid == 0) *stkt = (int)atomicAdd(&g_ticket, 1u);
    __syncthreads();
    int u = *stkt;

    const int warp = tid >> 5, lane = tid & 31;
    const int wm  = (warp >> 1) * 64;
    const int wn  = (warp & 1) * 64;
    const int gid = lane >> 2;
    const int q   = lane & 3;
    const uint32_t a_lane = (uint32_t)((lane >> 4) * 16);
    const uint32_t b_loff = (uint32_t)(((lane & 7) + ((lane >> 4) & 1) * 8) * A_ROW_B
                                       + ((lane >> 3) & 1) * 16);

    int Ap = 0, Ac = 0;     // A chunk counters (cumulative)
    int Bp = 0;             // B producer counter (cumulative)
    int Bc = 0;             // B consumer counter (cumulative)

    #pragma unroll 1
    while (u < NUNITS) {
        const int l = u >> 9, m = u & 511;
        const int m0   = m << 8;
        const int base = (m0 > 136) ? (m0 - 136) : 0;
        const int CIN   = l ? 512 : 256;
        const int NC0   = CIN >> 5;               // 8 or 16 (power of 2)
        const int NITER = NC0 * KTAPS;
        const __half* X  = (l == 0) ? featH : ((l & 1) ? actA : actB);
        const __half* Wl = (l == 0) ? Wp : (Wp + W0H + (size_t)(l - 1) * WLH);
        const bool LAST = (l == 7);
        __half* OH = (l & 1) ? actB : actA;

        if (tid == 0) *stkt = (int)atomicAdd(&g_ticket, 1u);
        for (int i = tid; i < 512; i += 256) {
            sgam[i] = gamma[l * 512 + i];
            sbet[i] = beta[l * 512 + i];
        }
        #pragma unroll
        for (int t = 0; t < 9; t++) {
            const int i = t * 256 + tid;
            const int site = i / KTAPS, tap = i - site * KTAPS;
            const int nid = nbr[(size_t)m0 * KTAPS + i];
            const int slot = (nid < 0) ? ZSLOT : (nid - base);
            aslot[tap * 256 + site] = (uint32_t)(slot * A_ROW_B);
        }
        if (l > 0 && tid < 3) {
            const int mm = m - 1 + tid;
            if (mm >= 0 && mm < 512) {
                const int* fp = &g_flags[(l - 1) * 512 + mm];
                while (ld_acq(fp) == 0)
                    asm volatile("nanosleep.u32 128;");
            }
        }
        __syncthreads();
        const int u_next = *stkt;
        const bool pf_next = (u_next < NUNITS);
        const __half* WlN = Wp;
        if (pf_next) {
            const int ln = u_next >> 9;
            WlN = (ln == 0) ? Wp : (Wp + W0H + (size_t)(ln - 1) * WLH);
        }

        auto loadA = [&](int c0, int buf) {
            const uint32_t ab = smbase + (uint32_t)buf * A_BUF_B;
            #pragma unroll
            for (int t = 0; t < 9; t++) {
                const int g = t * 256 + tid;
                if (g < 528 * 4) {
                    const int row = g >> 2, seg = g & 3;
                    const long gr = (long)base + row;
                    const bool ok = gr < NSITES;
                    const __half* src = ok ? (X + gr * CIN + c0 * 32 + seg * 8) : X;
                    cp16(ab + (uint32_t)(row * A_ROW_B + seg * 16), src, ok ? 16 : 0);
                }
            }
        };
        auto loadBr = [&](int s, const __half* wc, int n0p) {
            const uint32_t bb = smbase + B_OFF + (uint32_t)s * B_STAGE_B;
            #pragma unroll
            for (int t = 0; t < 2; t++) {
                const int g = t * 256 + tid;
                const int nl = g >> 2, seg = g & 3;
                cp16(bb + (uint32_t)(nl * A_ROW_B + seg * 16),
                     wc + (size_t)(n0p + nl) * 32 + seg * 8, 16);
            }
        };

        // ---- A prologue: chunk 0 of this unit ----
        {
            const int b = Ap & 1, r = Ap >> 1;
            if (r >= 1) mbar_wait(EA(b), (uint32_t)((r - 1) & 1));
            loadA(0, b);
            cp_arrive(FA(b));
            Ap++;
        }
        // ---- B prologue: first unit of this CTA only ----
        if (Bp == 0) {
            #pragma unroll 1
            for (int p = 0; p < 6; p++) {
                loadBr(p, Wl + (size_t)p * 16384, 0);
                cp_arrive(FB(p));
                Bp++;
            }
        }
        int pcp = 6, pnb = 0;        // B produce cursor (pnb==4 => next unit)
        const int Ac0 = Ac;

        #pragma unroll 1
        for (int nb = 0; nb < 4; nb++) {
            const int n0 = nb << 7;
            float d[4][8][4];
            #pragma unroll
            for (int i = 0; i < 4; i++)
                #pragma unroll
                for (int j = 0; j < 8; j++)
                    #pragma unroll
                    for (int r = 0; r < 4; r++) d[i][j][r] = 0.f;

            #pragma unroll 1
            for (int it = 0; it < NITER; it++) {
                const int c0 = it / KTAPS, tap = it - c0 * KTAPS;

                // --- B producer: exactly one chunk per iteration ---
                if (pnb < 4 || (pnb == 4 && pcp < 6 && pf_next)) {
                    const __half* wsrc = (pnb < 4) ? (Wl + (size_t)pcp * 16384)
                                                   : (WlN + (size_t)pcp * 16384);
                    const int n0p = (pnb < 4) ? (pnb << 7) : 0;
                    const int s = Bp & 7, r = Bp >> 3;
                    if (r >= 1) mbar_wait(EB(s), (uint32_t)((r - 1) & 1));
                    loadBr(s, wsrc, n0p);
                    cp_arrive(FB(s));
                    Bp++;
                    const int lim = (pnb < 4) ? NITER : 6;
                    if (++pcp == lim) { pcp = 0; pnb++; }
                }
                // --- A producer: next chunk in the flattened per-unit stream ---
                if (tap == 1) {
                    const int la = Ac - Ac0;          // chunk currently consumed
                    if (la + 1 < 4 * NC0) {
                        const int b = Ap & 1, r = Ap >> 1;
                        if (r >= 1) mbar_wait(EA(b), (uint32_t)((r - 1) & 1));
                        loadA((la + 1) & (NC0 - 1), b);
                        cp_arrive(FA(b));
                        Ap++;
                    }
                }

                // --- consumers ---
                if (tap == 0) mbar_wait(FA(Ac & 1), (uint32_t)((Ac >> 1) & 1));
                mbar_wait(FB(Bc & 7), (uint32_t)((Bc >> 3) & 1));

                const uint32_t ab = smbase + (uint32_t)(Ac & 1) * A_BUF_B;
                const uint32_t bb = smbase + B_OFF + (uint32_t)(Bc & 7) * B_STAGE_B;
                uint32_t asl[4];
                #pragma unroll
                for (int mt = 0; mt < 4; mt++)
                    asl[mt] = aslot[tap * 256 + wm + mt * 16 + (lane & 15)];
                #pragma unroll
                for (int s16 = 0; s16 < 2; s16++) {
                    uint32_t a[4][4];
                    #pragma unroll
                    for (int mt = 0; mt < 4; mt++)
                        ldmx4(a[mt], ab + asl[mt] + (uint32_t)(s16 * 32) + a_lane);
                    uint32_t b[8][2];
                    #pragma unroll
                    for (int np = 0; np < 4; np++) {
                        uint32_t r[4];
                        ldmx4(r, bb + (uint32_t)((wn + np * 16) * A_ROW_B + s16 * 32)
                                 + b_loff);
                        b[2 * np][0] = r[0];     b[2 * np][1] = r[1];
                        b[2 * np + 1][0] = r[2]; b[2 * np + 1][1] = r[3];
                    }
                    #pragma unroll
                    for (int nt = 0; nt < 8; nt++)
                        #pragma unroll
                        for (int mt = 0; mt < 4; mt++)
                            mma16(d[mt][nt], a[mt], b[nt]);
                }

                mbar_arrive(EB(Bc & 7)); Bc++;
                if (tap == KTAPS - 1) { mbar_arrive(EA(Ac & 1)); Ac++; }
            }

            // ---- fused GroupNorm(16-ch) + ReLU epilogue for this n-block ----
            #pragma unroll
            for (int mt = 0; mt < 4; mt++) {
                #pragma unroll
                for (int h = 0; h < 2; h++) {
                    const int row = m0 + wm + mt * 16 + gid + h * 8;
                    const size_t rbase = (size_t)row * HID + n0 + wn;
                    #pragma unroll
                    for (int g = 0; g < 4; g++) {
                        const float v0 = d[mt][2 * g    ][2 * h];
                        const float v1 = d[mt][2 * g    ][2 * h + 1];
                        const float v2 = d[mt][2 * g + 1][2 * h];
                        const float v3 = d[mt][2 * g + 1][2 * h + 1];
                        float s  = v0 + v1 + v2 + v3;
                        float ss = v0 * v0 + v1 * v1 + v2 * v2 + v3 * v3;
                        s  += __shfl_xor_sync(0xffffffffu, s, 1);
                        ss += __shfl_xor_sync(0xffffffffu, ss, 1);
                        s  += __shfl_xor_sync(0xffffffffu, s, 2);
                        ss += __shfl_xor_sync(0xffffffffu, ss, 2);
                        const float mu  = s * (1.f / 16.f);
                        const float var = ss * (1.f / 16.f) - mu * mu;
                        const float rs  = rsqrtf(var + EPS);
                        const int cb = n0 + wn + 16 * g + 2 * q;
                        const float o0 = fmaxf(fmaf((v0 - mu) * rs, sgam[cb],     sbet[cb]),     0.f);
                        const float o1 = fmaxf(fmaf((v1 - mu) * rs, sgam[cb + 1], sbet[cb + 1]), 0.f);
                        const float o2 = fmaxf(fmaf((v2 - mu) * rs, sgam[cb + 8], sbet[cb + 8]), 0.f);
                        const float o3 = fmaxf(fmaf((v3 - mu) * rs, sgam[cb + 9], sbet[cb + 9]), 0.f);
                        if (LAST) {
                            *(float2*)(outF + rbase + 16 * g + 2 * q)     = make_float2(o0, o1);
                            *(float2*)(outF + rbase + 16 * g + 8 + 2 * q) = make_float2(o2, o3);
                        } else {
                            *(__half2*)(OH + rbase + 16 * g + 2 * q)     = __floats2half2_rn(o0, o1);
                            *(__half2*)(OH + rbase + 16 * g + 8 + 2 * q) = __floats2half2_rn(o2, o3);
                        }
                    }
                }
            }
        }

        __threadfence();
        __syncthreads();
        if (tid == 0) st_rel(&g_flags[u], 1);
        u = u_next;
    }
}

// ---------------------------------------------------------------------------
// Prep kernels
// ---------------------------------------------------------------------------
__global__ void reset_flags()
{
    const int i = blockIdx.x * 256 + threadIdx.x;
    g_flags[i] = 0;
    if (i == 0) g_ticket = 0u;
}
__global__ void w_prep(const float* __restrict__ W, __half* __restrict__ Wp, int CPT)
{
    __shared__ float t[32][33];
    const int bx = blockIdx.x;
    const int by = blockIdx.y;
    const int x = threadIdx.x, y = threadIdx.y;
    #pragma unroll
    for (int i = 0; i < 32; i += 8)
        t[y + i][x] = W[(size_t)(by * 32 + y + i) * 512 + bx * 32 + x];
    __syncthreads();
    const int tap = by / CPT, c0 = by - tap * CPT;
    const int cpos = c0 * KTAPS + tap;
    #pragma unroll
    for (int i = 0; i < 32; i += 8) {
        const int nl = y + i, kk = x;
        Wp[(size_t)cpos * 16384 + (size_t)(bx * 32 + nl) * 32 + kk] =
            __float2half_rn(t[kk][nl]);
    }
}
__global__ void f2h(const float* __restrict__ src, __half* __restrict__ dst)
{
    const int t = blockIdx.x * blockDim.x + threadIdx.x;
    const float4* s = (const float4*)src + 2 * (size_t)t;
    const float4 v0 = s[0], v1 = s[1];
    __half2* o = (__half2*)dst + 4 * (size_t)t;
    o[0] = __floats2half2_rn(v0.x, v0.y);
    o[1] = __floats2half2_rn(v0.z, v0.w);
    o[2] = __floats2half2_rn(v1.x, v1.y);
    o[3] = __floats2half2_rn(v1.z, v1.w);
}

// ===========================================================================
// kernel_launch: prep + flag/ticket reset + one persistent fused kernel,
// one CTA per SM (queried at launch; pure attribute read, capture-legal).
// ===========================================================================
extern "C" void kernel_launch(void* const* d_in, const int* in_sizes, int n_in,
                              void* d_out, int out_size)
{
    const float* feat  = (const float*)d_in[0];
    const int*   nbr   = (const int*)  d_in[1];
    const float* w0    = (const float*)d_in[2];
    const float* wrest = (const float*)d_in[3];
    const float* gamma = (const float*)d_in[4];
    const float* beta  = (const float*)d_in[5];

    __half *actA, *actB, *featH, *Wp;
    cudaGetSymbolAddress((void**)&actA, g_actA);
    cudaGetSymbolAddress((void**)&actB, g_actB);
    cudaGetSymbolAddress((void**)&featH, g_featH);
    cudaGetSymbolAddress((void**)&Wp, g_Wp);

    int dev = 0, sms = 148;
    cudaGetDevice(&dev);
    cudaDeviceGetAttribute(&sms, cudaDevAttrMultiProcessorCount, dev);
    if (sms < 1 || sms > NUNITS) sms = 148;

    cudaFuncSetAttribute(spconv_all,
                         cudaFuncAttributeMaxDynamicSharedMemorySize, SMEM_BYTES);

    f2h<<<(NSITES * 256 / 8) / 256, 256>>>(feat, featH);
    w_prep<<<dim3(16, 72), dim3(32, 8)>>>(w0, Wp, 8);
    for (int l = 0; l < 7; l++)
        w_prep<<<dim3(16, 144), dim3(32, 8)>>>(
            wrest + (size_t)l * 4608 * 512, Wp + W0H + (size_t)l * WLH, 16);
    reset_flags<<<NUNITS / 256, 256>>>();

    spconv_all<<<sms, 256, SMEM_BYTES>>>(featH, nbr, Wp, gamma, beta,
                                         actA, actB, (float*)d_out);
}